// round 1
// baseline (speedup 1.0000x reference)
#include <cuda_runtime.h>

#define NN 50000
#define NE 800000
#define FDIM 128
#define HDIM 64
#define NG 512
#define NC 10
#define NB_SCAN ((NN + 1023) / 1024)   /* 49 */

#define SMEM_G128 ((128*128 + 128*68) * 4)  /* 100352 */
#define SMEM_G64  ((64*128  + 64*68)  * 4)  /* 50176  */
#define SMEM_TOPK (8192 * 8)                /* 65536  */

// ---------------- scratch (static device globals; no runtime alloc) ----------
__device__ float g_y[NN * 128];          // GEMM outputs [yl | yr]
__device__ float g_h1[NN * 64];          // h1, later reused for h3
__device__ float g_h2[NN * 64];
__device__ float g_scores[NE];
__device__ float g_ew[NE];
__device__ unsigned long long g_buckets[NE];
__device__ int g_srcs[NE];
__device__ int g_eids[NE];
__device__ int g_deg[NN];
__device__ int g_rowptr[NN + 1];
__device__ int g_cursor[NN];
__device__ int g_part[64];
__device__ int g_segcnt[NG];
__device__ int g_segptr[NG + 1];
__device__ int g_segcur[NG];
__device__ int g_nodecnt[NG];
__device__ int g_nodeptr[NG + 1];
__device__ float g_pooled[NG * 64];

// ---------------- init / histogram ----------------
__global__ void k_zero() {
    int i = blockIdx.x * blockDim.x + threadIdx.x;
    if (i < NN) g_deg[i] = 0;
    if (i < NG) { g_segcnt[i] = 0; g_nodecnt[i] = 0; }
}

__global__ void k_hist(const int* __restrict__ src, const int* __restrict__ dst,
                       const int* __restrict__ batch) {
    int i = blockIdx.x * blockDim.x + threadIdx.x;
    if (i < NE) {
        atomicAdd(&g_deg[dst[i]], 1);
        atomicAdd(&g_segcnt[batch[src[i]]], 1);
    }
    if (i < NN) atomicAdd(&g_nodecnt[batch[i]], 1);
}

// ---------------- scans ----------------
__global__ void k_scan_block() {
    __shared__ int s[1024];
    int t = threadIdx.x;
    int i = blockIdx.x * 1024 + t;
    int v = (i < NN) ? g_deg[i] : 0;
    s[t] = v; __syncthreads();
    for (int off = 1; off < 1024; off <<= 1) {
        int a = (t >= off) ? s[t - off] : 0; __syncthreads();
        s[t] += a; __syncthreads();
    }
    if (i < NN) g_rowptr[i + 1] = s[t];
    if (t == 1023) g_part[blockIdx.x] = s[1023];
}

__device__ __forceinline__ int blk_scan_inc(int v, int* s) {
    int t = threadIdx.x;
    s[t] = v; __syncthreads();
    for (int off = 1; off < 1024; off <<= 1) {
        int a = (t >= off) ? s[t - off] : 0; __syncthreads();
        s[t] += a; __syncthreads();
    }
    int r = s[t]; __syncthreads();
    return r;
}

__global__ void k_scan_small() {
    __shared__ int s[1024];
    int t = threadIdx.x;
    int v = (t < NB_SCAN) ? g_part[t] : 0;
    int inc = blk_scan_inc(v, s);
    if (t < NB_SCAN) g_part[t] = inc - v;             // exclusive

    v = (t < NG) ? g_segcnt[t] : 0;
    inc = blk_scan_inc(v, s);
    if (t < NG) g_segptr[t + 1] = inc;
    if (t == 0) g_segptr[0] = 0;

    v = (t < NG) ? g_nodecnt[t] : 0;
    inc = blk_scan_inc(v, s);
    if (t < NG) g_nodeptr[t + 1] = inc;
    if (t == 0) g_nodeptr[0] = 0;
}

__global__ void k_scan_add() {
    int i = blockIdx.x * blockDim.x + threadIdx.x;
    if (i < NN) g_rowptr[i + 1] += g_part[i >> 10];
    if (i == 0) g_rowptr[0] = 0;
}

__global__ void k_cursor() {
    int i = blockIdx.x * blockDim.x + threadIdx.x;
    if (i < NN) g_cursor[i] = g_rowptr[i];
    if (i < NG) g_segcur[i] = g_segptr[i];
}

// ---------------- CSR build (counting sort by dst) ----------------
__global__ void k_scatter(const int* __restrict__ src, const int* __restrict__ dst) {
    int e = blockIdx.x * blockDim.x + threadIdx.x;
    if (e >= NE) return;
    int p = atomicAdd(&g_cursor[dst[e]], 1);
    g_srcs[p] = src[e];
    g_eids[p] = e;
}

// stabilize per-dst edge order by edge id (determinism of fp add order)
__global__ void k_sortadj() {
    __shared__ unsigned long long buf[8][128];
    int w = (blockIdx.x * blockDim.x + threadIdx.x) >> 5;
    int lane = threadIdx.x & 31;
    int lw = threadIdx.x >> 5;
    if (w >= NN) return;
    int s0 = g_rowptr[w];
    int cnt = g_rowptr[w + 1] - s0;
    if (cnt <= 1 || cnt > 128) return;
    unsigned long long* b = buf[lw];
    for (int i = lane; i < cnt; i += 32)
        b[i] = ((unsigned long long)(unsigned)g_eids[s0 + i] << 32) | (unsigned)g_srcs[s0 + i];
    __syncwarp();
    for (int p = 0; p < cnt; p++) {
        for (int l = (p & 1) + 2 * lane; l + 1 < cnt; l += 64) {
            unsigned long long a = b[l], c = b[l + 1];
            if (a > c) { b[l] = c; b[l + 1] = a; }
        }
        __syncwarp();
    }
    for (int i = lane; i < cnt; i += 32) {
        unsigned long long v = b[i];
        g_eids[s0 + i] = (int)(v >> 32);
        g_srcs[s0 + i] = (int)(v & 0xffffffffu);
    }
}

// ---------------- GEMM: g_y[N,128] = A[N,K] @ [Wa | Wb] (Wa,Wb each K x 64) ----
template<int K>
__global__ __launch_bounds__(256) void k_gemm(const float* __restrict__ A,
                                              const float* __restrict__ Wa,
                                              const float* __restrict__ Wb) {
    extern __shared__ float sm[];
    float* Ws = sm;             // K * 128
    float* As = sm + K * 128;   // K * 68 (padded, transposed)
    int tid = threadIdx.x;
    for (int idx = tid; idx < K * 64; idx += 256) {
        int k = idx >> 6, c = idx & 63;
        Ws[k * 128 + c] = Wa[idx];
        Ws[k * 128 + 64 + c] = Wb[idx];
    }
    int row0 = blockIdx.x * 64;
    for (int idx = tid; idx < 64 * K; idx += 256) {
        int r = idx / K, k = idx - r * K;
        int row = row0 + r;
        As[k * 68 + r] = (row < NN) ? A[row * K + k] : 0.f;
    }
    __syncthreads();
    int tx = tid & 15, ty = tid >> 4;
    float acc[4][8];
#pragma unroll
    for (int i = 0; i < 4; i++)
#pragma unroll
        for (int j = 0; j < 8; j++) acc[i][j] = 0.f;

#pragma unroll 8
    for (int k = 0; k < K; k++) {
        float4 a  = *(const float4*)&As[k * 68 + ty * 4];
        float4 w0 = *(const float4*)&Ws[k * 128 + tx * 8];
        float4 w1 = *(const float4*)&Ws[k * 128 + tx * 8 + 4];
        float av[4] = {a.x, a.y, a.z, a.w};
        float wv[8] = {w0.x, w0.y, w0.z, w0.w, w1.x, w1.y, w1.z, w1.w};
#pragma unroll
        for (int i = 0; i < 4; i++)
#pragma unroll
            for (int j = 0; j < 8; j++)
                acc[i][j] += av[i] * wv[j];
    }
#pragma unroll
    for (int i = 0; i < 4; i++) {
        int row = row0 + ty * 4 + i;
        if (row < NN) {
            float4 o0 = make_float4(acc[i][0], acc[i][1], acc[i][2], acc[i][3]);
            float4 o1 = make_float4(acc[i][4], acc[i][5], acc[i][6], acc[i][7]);
            *(float4*)&g_y[row * 128 + tx * 8] = o0;
            *(float4*)&g_y[row * 128 + tx * 8 + 4] = o1;
        }
    }
}

// ---------------- segment aggregation (warp per dst node) ----------------
template<bool WEIGHTED>
__global__ void k_agg(const float* __restrict__ bias, float* __restrict__ hout) {
    int w = (blockIdx.x * blockDim.x + threadIdx.x) >> 5;
    int lane = threadIdx.x & 31;
    if (w >= NN) return;
    int s0 = g_rowptr[w], s1 = g_rowptr[w + 1];
    float ax = 0.f, ay = 0.f;
    for (int base = s0; base < s1; base += 32) {
        int m = min(32, s1 - base);
        int msrc = 0; float mw = 0.f;
        if (lane < m) {
            msrc = g_srcs[base + lane];
            if (WEIGHTED) mw = g_ew[g_eids[base + lane]];
        }
        for (int j = 0; j < m; j++) {
            int src = __shfl_sync(0xffffffffu, msrc, j);
            float2 v = *(const float2*)&g_y[src * 128 + lane * 2];
            if (WEIGHTED) {
                float ww = __shfl_sync(0xffffffffu, mw, j);
                ax += ww * v.x; ay += ww * v.y;
            } else {
                ax += v.x; ay += v.y;
            }
        }
    }
    float dg = fmaxf((float)(s1 - s0), 1.f);
    int c = lane * 2;
    float r0 = ax / dg + bias[c]     + g_y[w * 128 + 64 + c];
    float r1 = ay / dg + bias[c + 1] + g_y[w * 128 + 64 + c + 1];
    hout[w * 64 + c]     = fmaxf(r0, 0.f);
    hout[w * 64 + c + 1] = fmaxf(r1, 0.f);
}

// ---------------- edge scores + segment bucketing ----------------
__global__ void k_score(const int* __restrict__ src, const int* __restrict__ dst,
                        const int* __restrict__ batch) {
    int e = blockIdx.x * 32 + (threadIdx.x >> 3);
    int j = threadIdx.x & 7;
    if (e >= NE) return;
    int s = src[e], d = dst[e];
    const float4* hs = (const float4*)&g_h1[s * 64 + j * 8];
    const float4* hd = (const float4*)&g_h1[d * 64 + j * 8];
    float4 a0 = hs[0], a1 = hs[1], b0 = hd[0], b1 = hd[1];
    float v = a0.x * b0.x + a0.y * b0.y + a0.z * b0.z + a0.w * b0.w
            + a1.x * b1.x + a1.y * b1.y + a1.z * b1.z + a1.w * b1.w;
    v += __shfl_xor_sync(0xffffffffu, v, 1);
    v += __shfl_xor_sync(0xffffffffu, v, 2);
    v += __shfl_xor_sync(0xffffffffu, v, 4);
    if (j == 0) {
        g_scores[e] = v;
        unsigned int u = __float_as_uint(v);
        u = (u & 0x80000000u) ? ~u : (u | 0x80000000u);
        unsigned long long key = ((unsigned long long)u << 32) | (unsigned)(~(unsigned)e);
        int g = batch[s];
        int p = atomicAdd(&g_segcur[g], 1);
        g_buckets[p] = key;
    }
}

// ---------------- per-graph exact top-k (bitonic sort of (score, eid) keys) ---
__global__ void k_topk(float* __restrict__ sampled) {
    extern __shared__ unsigned long long sk[];
    int g = blockIdx.x;
    int s0 = g_segptr[g];
    int n = g_segptr[g + 1] - s0;
    if (n <= 0) return;
    int m = 1;
    while (m < n) m <<= 1;
    if (m > 8192) m = 8192;           // safety; never hit for this data
    int nn2 = min(n, m);
    for (int i = threadIdx.x; i < m; i += blockDim.x)
        sk[i] = (i < nn2) ? g_buckets[s0 + i] : 0ull;
    __syncthreads();
    for (int k2 = 2; k2 <= m; k2 <<= 1) {
        for (int jj = k2 >> 1; jj > 0; jj >>= 1) {
            for (int i = threadIdx.x; i < m; i += blockDim.x) {
                int ij = i ^ jj;
                if (ij > i) {
                    unsigned long long a = sk[i], b = sk[ij];
                    bool desc = ((i & k2) == 0);
                    if (desc ? (a < b) : (a > b)) { sk[i] = b; sk[ij] = a; }
                }
            }
            __syncthreads();
        }
    }
    int k = (n + 1) >> 1;             // ceil(0.5 * n)
    for (int i = threadIdx.x; i < nn2; i += blockDim.x) {
        unsigned int eid = ~(unsigned int)(sk[i] & 0xffffffffu);
        float sel = (i < k) ? 1.f : 0.f;
        sampled[eid] = sel;
        g_ew[eid] = sel * g_scores[eid];
    }
}

// ---------------- pooling + MLP head ----------------
__global__ void k_pool() {
    int g = blockIdx.x, t = threadIdx.x;
    int s0 = g_nodeptr[g], s1 = g_nodeptr[g + 1];
    float acc = 0.f;
    for (int i = s0; i < s1; i++) acc += g_h1[i * 64 + t];   // h3 lives in g_h1
    g_pooled[g * 64 + t] = acc / fmaxf((float)(s1 - s0), 1.f);
}

__global__ void k_head(const float* __restrict__ W1, const float* __restrict__ b1,
                       const float* __restrict__ W2, const float* __restrict__ b2,
                       float* __restrict__ out) {
    __shared__ float p[64], z1[64], z2[10];
    int g = blockIdx.x, t = threadIdx.x;
    p[t] = g_pooled[g * 64 + t];
    __syncthreads();
    float acc = b1[t];
    for (int k = 0; k < 64; k++) acc += p[k] * W1[k * 64 + t];
    z1[t] = fmaxf(acc, 0.f);
    __syncthreads();
    if (t < NC) {
        float a2 = b2[t];
        for (int k = 0; k < 64; k++) a2 += z1[k] * W2[k * 10 + t];
        z2[t] = a2;
    }
    __syncthreads();
    if (t == 0) {
        float mx = z2[0];
        for (int c = 1; c < NC; c++) mx = fmaxf(mx, z2[c]);
        float se = 0.f;
        for (int c = 0; c < NC; c++) se += expf(z2[c] - mx);
        float lse = mx + logf(se);
        for (int c = 0; c < NC; c++) out[g * NC + c] = z2[c] - lse;
    }
}

// ---------------- launcher ----------------
extern "C" void kernel_launch(void* const* d_in, const int* in_sizes, int n_in,
                              void* d_out, int out_size) {
    const float* x   = (const float*)d_in[0];
    const int*   ei  = (const int*)d_in[1];
    const int*   bat = (const int*)d_in[2];
    const float* W1l = (const float*)d_in[3];
    const float* b1l = (const float*)d_in[4];
    const float* W1r = (const float*)d_in[5];
    const float* W2l = (const float*)d_in[6];
    const float* b2l = (const float*)d_in[7];
    const float* W2r = (const float*)d_in[8];
    const float* W3l = (const float*)d_in[9];
    const float* b3l = (const float*)d_in[10];
    const float* W3r = (const float*)d_in[11];
    const float* Wl1 = (const float*)d_in[12];
    const float* bl1 = (const float*)d_in[13];
    const float* Wl2 = (const float*)d_in[14];
    const float* bl2 = (const float*)d_in[15];
    const int* src = ei;
    const int* dst = ei + NE;
    float* out_logits  = (float*)d_out;
    float* out_sampled = (float*)d_out + NG * NC;

    float *p_h1, *p_h2;
    cudaGetSymbolAddress((void**)&p_h1, g_h1);
    cudaGetSymbolAddress((void**)&p_h2, g_h2);

    cudaFuncSetAttribute((const void*)k_gemm<128>,
                         cudaFuncAttributeMaxDynamicSharedMemorySize, SMEM_G128);
    cudaFuncSetAttribute((const void*)k_gemm<64>,
                         cudaFuncAttributeMaxDynamicSharedMemorySize, SMEM_G64);
    cudaFuncSetAttribute((const void*)k_topk,
                         cudaFuncAttributeMaxDynamicSharedMemorySize, SMEM_TOPK);

    // graph structure (recomputed each call; deterministic result)
    k_zero<<<196, 256>>>();
    k_hist<<<(NE + 255) / 256, 256>>>(src, dst, bat);
    k_scan_block<<<NB_SCAN, 1024>>>();
    k_scan_small<<<1, 1024>>>();
    k_scan_add<<<196, 256>>>();
    k_cursor<<<196, 256>>>();
    k_scatter<<<(NE + 255) / 256, 256>>>(src, dst);
    k_sortadj<<<(NN * 32 + 255) / 256, 256>>>();

    // layer 1
    k_gemm<128><<<(NN + 63) / 64, 256, SMEM_G128>>>(x, W1l, W1r);
    k_agg<false><<<(NN * 32 + 255) / 256, 256>>>(b1l, p_h1);

    // edge scores + per-graph top-k
    k_score<<<(NE + 31) / 32, 256>>>(src, dst, bat);
    k_topk<<<NG, 512, SMEM_TOPK>>>(out_sampled);

    // layer 2
    k_gemm<64><<<(NN + 63) / 64, 256, SMEM_G64>>>(p_h1, W2l, W2r);
    k_agg<true><<<(NN * 32 + 255) / 256, 256>>>(b2l, p_h2);

    // layer 3 (h3 -> g_h1)
    k_gemm<64><<<(NN + 63) / 64, 256, SMEM_G64>>>(p_h2, W3l, W3r);
    k_agg<true><<<(NN * 32 + 255) / 256, 256>>>(b3l, p_h1);

    // pooling + head
    k_pool<<<NG, 64>>>();
    k_head<<<NG, 64>>>(Wl1, bl1, Wl2, bl2, out_logits);
}

// round 2
// speedup vs baseline: 1.0277x; 1.0277x over previous
#include <cuda_runtime.h>

#define NN 50000
#define NE 800000
#define FDIM 128
#define HDIM 64
#define NG 512
#define NC 10
#define NB_SCAN ((NN + 1023) / 1024)   /* 49 */

#define SMEM_G128 ((128*128 + 128*68) * 4)  /* 100352 */
#define SMEM_G64  ((64*128  + 64*68)  * 4)  /* 50176  */
#define SMEM_TOPK (8192 * 8)                /* 65536  */

// ---------------- scratch (static device globals; no runtime alloc) ----------
__device__ float g_yl[NN * 64];          // GEMM left output (gathered randomly)
__device__ float g_yr[NN * 64];          // GEMM right output (streamed)
__device__ float g_h1[NN * 64];          // h1, later reused for h3
__device__ float g_h2[NN * 64];
__device__ float g_scores[NE];
__device__ float g_ew[NE];
__device__ unsigned long long g_buckets[NE];
__device__ unsigned long long g_adj[NE]; // (eid<<32)|src, CSR by dst
__device__ int g_deg[NN];
__device__ int g_rowptr[NN + 1];
__device__ int g_cursor[NN];
__device__ int g_part[64];
__device__ int g_segcnt[NG];
__device__ int g_segptr[NG + 1];
__device__ int g_segcur[NG];
__device__ int g_nodecnt[NG];
__device__ int g_nodeptr[NG + 1];

// ---------------- init / histogram ----------------
__global__ void k_zero() {
    int i = blockIdx.x * blockDim.x + threadIdx.x;
    if (i < NN) g_deg[i] = 0;
    if (i < NG) { g_segcnt[i] = 0; g_nodecnt[i] = 0; }
}

__global__ void k_hist(const int* __restrict__ src, const int* __restrict__ dst,
                       const int* __restrict__ batch) {
    int i = blockIdx.x * blockDim.x + threadIdx.x;
    if (i < NE) {
        atomicAdd(&g_deg[dst[i]], 1);
        atomicAdd(&g_segcnt[batch[src[i]]], 1);
    }
    if (i < NN) atomicAdd(&g_nodecnt[batch[i]], 1);
}

// ---------------- scans ----------------
__global__ void k_scan_block() {
    __shared__ int s[1024];
    int t = threadIdx.x;
    int i = blockIdx.x * 1024 + t;
    int v = (i < NN) ? g_deg[i] : 0;
    s[t] = v; __syncthreads();
    for (int off = 1; off < 1024; off <<= 1) {
        int a = (t >= off) ? s[t - off] : 0; __syncthreads();
        s[t] += a; __syncthreads();
    }
    if (i < NN) g_rowptr[i + 1] = s[t];
    if (t == 1023) g_part[blockIdx.x] = s[1023];
}

__device__ __forceinline__ int blk_scan_inc(int v, int* s) {
    int t = threadIdx.x;
    s[t] = v; __syncthreads();
    for (int off = 1; off < 1024; off <<= 1) {
        int a = (t >= off) ? s[t - off] : 0; __syncthreads();
        s[t] += a; __syncthreads();
    }
    int r = s[t]; __syncthreads();
    return r;
}

__global__ void k_scan_small() {
    __shared__ int s[1024];
    int t = threadIdx.x;
    int v = (t < NB_SCAN) ? g_part[t] : 0;
    int inc = blk_scan_inc(v, s);
    if (t < NB_SCAN) g_part[t] = inc - v;             // exclusive

    v = (t < NG) ? g_segcnt[t] : 0;
    inc = blk_scan_inc(v, s);
    if (t < NG) { g_segptr[t + 1] = inc; g_segcur[t] = inc - v; }
    if (t == 0) g_segptr[0] = 0;

    v = (t < NG) ? g_nodecnt[t] : 0;
    inc = blk_scan_inc(v, s);
    if (t < NG) g_nodeptr[t + 1] = inc;
    if (t == 0) g_nodeptr[0] = 0;
}

__global__ void k_scan_addcur() {
    int i = blockIdx.x * blockDim.x + threadIdx.x;
    if (i < NN) {
        int v = g_rowptr[i + 1] + g_part[i >> 10];
        g_rowptr[i + 1] = v;
        if (i + 1 < NN) g_cursor[i + 1] = v;
    }
    if (i == 0) { g_rowptr[0] = 0; g_cursor[0] = 0; }
}

// ---------------- CSR build (counting sort by dst) ----------------
__global__ void k_scatter(const int* __restrict__ src, const int* __restrict__ dst) {
    int e = blockIdx.x * blockDim.x + threadIdx.x;
    if (e >= NE) return;
    int p = atomicAdd(&g_cursor[dst[e]], 1);
    g_adj[p] = ((unsigned long long)(unsigned)e << 32) | (unsigned)src[e];
}

// stabilize per-dst edge order by edge id (determinism of fp add order)
__global__ void k_sortadj() {
    __shared__ unsigned long long buf[8][128];
    int w = (blockIdx.x * blockDim.x + threadIdx.x) >> 5;
    int lane = threadIdx.x & 31;
    int lw = threadIdx.x >> 5;
    if (w >= NN) return;
    int s0 = g_rowptr[w];
    int cnt = g_rowptr[w + 1] - s0;
    if (cnt <= 1 || cnt > 128) return;
    unsigned long long* b = buf[lw];
    for (int i = lane; i < cnt; i += 32) b[i] = g_adj[s0 + i];
    __syncwarp();
    for (int p = 0; p < cnt; p++) {
        for (int l = (p & 1) + 2 * lane; l + 1 < cnt; l += 64) {
            unsigned long long a = b[l], c = b[l + 1];
            if (a > c) { b[l] = c; b[l + 1] = a; }
        }
        __syncwarp();
    }
    for (int i = lane; i < cnt; i += 32) g_adj[s0 + i] = b[i];
}

// ---------------- GEMM: [yl | yr] = A[N,K] @ [Wa | Wb] (Wa,Wb each K x 64) ----
template<int K>
__global__ __launch_bounds__(256) void k_gemm(const float* __restrict__ A,
                                              const float* __restrict__ Wa,
                                              const float* __restrict__ Wb) {
    extern __shared__ float sm[];
    float* Ws = sm;             // K * 128
    float* As = sm + K * 128;   // K * 68 (padded, transposed)
    int tid = threadIdx.x;
    for (int idx = tid; idx < K * 64; idx += 256) {
        int k = idx >> 6, c = idx & 63;
        Ws[k * 128 + c] = Wa[idx];
        Ws[k * 128 + 64 + c] = Wb[idx];
    }
    int row0 = blockIdx.x * 64;
    for (int idx = tid; idx < 64 * K; idx += 256) {
        int r = idx / K, k = idx - r * K;
        int row = row0 + r;
        As[k * 68 + r] = (row < NN) ? A[row * K + k] : 0.f;
    }
    __syncthreads();
    int tx = tid & 15, ty = tid >> 4;
    float acc[4][8];
#pragma unroll
    for (int i = 0; i < 4; i++)
#pragma unroll
        for (int j = 0; j < 8; j++) acc[i][j] = 0.f;

#pragma unroll 8
    for (int k = 0; k < K; k++) {
        float4 a  = *(const float4*)&As[k * 68 + ty * 4];
        float4 w0 = *(const float4*)&Ws[k * 128 + tx * 8];
        float4 w1 = *(const float4*)&Ws[k * 128 + tx * 8 + 4];
        float av[4] = {a.x, a.y, a.z, a.w};
        float wv[8] = {w0.x, w0.y, w0.z, w0.w, w1.x, w1.y, w1.z, w1.w};
#pragma unroll
        for (int i = 0; i < 4; i++)
#pragma unroll
            for (int j = 0; j < 8; j++)
                acc[i][j] += av[i] * wv[j];
    }
    int c = tx * 8;
#pragma unroll
    for (int i = 0; i < 4; i++) {
        int row = row0 + ty * 4 + i;
        if (row < NN) {
            float* dstp = (c < 64) ? &g_yl[row * 64 + c] : &g_yr[row * 64 + c - 64];
            *(float4*)dstp       = make_float4(acc[i][0], acc[i][1], acc[i][2], acc[i][3]);
            *(float4*)(dstp + 4) = make_float4(acc[i][4], acc[i][5], acc[i][6], acc[i][7]);
        }
    }
}

// ---------------- segment aggregation (warp per dst node, half-warp per edge) -
template<bool WEIGHTED>
__global__ void k_agg(const float* __restrict__ bias, float* __restrict__ hout) {
    int w = (blockIdx.x * blockDim.x + threadIdx.x) >> 5;
    int lane = threadIdx.x & 31;
    if (w >= NN) return;
    int grp = lane >> 4, sub = lane & 15;
    int s0 = g_rowptr[w], s1 = g_rowptr[w + 1];
    float4 acc = make_float4(0.f, 0.f, 0.f, 0.f);
    for (int p = s0 + grp; p < s1; p += 2) {
        unsigned long long ad = __ldg(&g_adj[p]);       // broadcast within half-warp
        int src = (int)(unsigned)ad;
        float wg;
        if (WEIGHTED) {
            wg = __ldg(&g_ew[(int)(ad >> 32)]);
            if (wg == 0.f) continue;                    // half-warp-uniform skip
        }
        float4 v = *(const float4*)&g_yl[src * 64 + sub * 4];
        if (WEIGHTED) {
            acc.x += wg * v.x; acc.y += wg * v.y; acc.z += wg * v.z; acc.w += wg * v.w;
        } else {
            acc.x += v.x; acc.y += v.y; acc.z += v.z; acc.w += v.w;
        }
    }
    acc.x += __shfl_xor_sync(0xffffffffu, acc.x, 16);
    acc.y += __shfl_xor_sync(0xffffffffu, acc.y, 16);
    acc.z += __shfl_xor_sync(0xffffffffu, acc.z, 16);
    acc.w += __shfl_xor_sync(0xffffffffu, acc.w, 16);
    if (grp == 0) {
        float dg = fmaxf((float)(s1 - s0), 1.f);
        int c = sub * 4;
        float4 b  = *(const float4*)&bias[c];
        float4 yr = *(const float4*)&g_yr[w * 64 + c];
        float4 o;
        o.x = fmaxf(acc.x / dg + b.x + yr.x, 0.f);
        o.y = fmaxf(acc.y / dg + b.y + yr.y, 0.f);
        o.z = fmaxf(acc.z / dg + b.z + yr.z, 0.f);
        o.w = fmaxf(acc.w / dg + b.w + yr.w, 0.f);
        *(float4*)&hout[w * 64 + c] = o;
    }
}

// ---------------- edge scores + segment bucketing ----------------
__global__ void k_score(const int* __restrict__ src, const int* __restrict__ dst,
                        const int* __restrict__ batch) {
    int e = blockIdx.x * 32 + (threadIdx.x >> 3);
    int j = threadIdx.x & 7;
    if (e >= NE) return;
    int s = src[e], d = dst[e];
    const float4* hs = (const float4*)&g_h1[s * 64 + j * 8];
    const float4* hd = (const float4*)&g_h1[d * 64 + j * 8];
    float4 a0 = hs[0], a1 = hs[1], b0 = hd[0], b1 = hd[1];
    float v = a0.x * b0.x + a0.y * b0.y + a0.z * b0.z + a0.w * b0.w
            + a1.x * b1.x + a1.y * b1.y + a1.z * b1.z + a1.w * b1.w;
    v += __shfl_xor_sync(0xffffffffu, v, 1);
    v += __shfl_xor_sync(0xffffffffu, v, 2);
    v += __shfl_xor_sync(0xffffffffu, v, 4);
    if (j == 0) {
        g_scores[e] = v;
        unsigned int u = __float_as_uint(v);
        u = (u & 0x80000000u) ? ~u : (u | 0x80000000u);
        unsigned long long key = ((unsigned long long)u << 32) | (unsigned)(~(unsigned)e);
        int g = batch[s];
        int p = atomicAdd(&g_segcur[g], 1);
        g_buckets[p] = key;
    }
}

// ---------------- per-graph exact top-k (bitonic sort of (score, eid) keys) ---
__global__ void k_topk(float* __restrict__ sampled) {
    extern __shared__ unsigned long long sk[];
    int g = blockIdx.x;
    int s0 = g_segptr[g];
    int n = g_segptr[g + 1] - s0;
    if (n <= 0) return;
    int m = 1;
    while (m < n) m <<= 1;
    if (m > 8192) m = 8192;           // safety; never hit for this data
    int nn2 = min(n, m);
    for (int i = threadIdx.x; i < m; i += blockDim.x)
        sk[i] = (i < nn2) ? g_buckets[s0 + i] : 0ull;
    __syncthreads();
    for (int k2 = 2; k2 <= m; k2 <<= 1) {
        for (int jj = k2 >> 1; jj > 0; jj >>= 1) {
            for (int i = threadIdx.x; i < m; i += blockDim.x) {
                int ij = i ^ jj;
                if (ij > i) {
                    unsigned long long a = sk[i], b = sk[ij];
                    bool desc = ((i & k2) == 0);
                    if (desc ? (a < b) : (a > b)) { sk[i] = b; sk[ij] = a; }
                }
            }
            __syncthreads();
        }
    }
    int k = (n + 1) >> 1;             // ceil(0.5 * n)
    for (int i = threadIdx.x; i < nn2; i += blockDim.x) {
        unsigned int eid = ~(unsigned int)(sk[i] & 0xffffffffu);
        float sel = (i < k) ? 1.f : 0.f;
        sampled[eid] = sel;
        g_ew[eid] = sel * g_scores[eid];
    }
}

// ---------------- pooling + MLP head (fused) ----------------
__global__ void k_poolhead(const float* __restrict__ W1, const float* __restrict__ b1,
                           const float* __restrict__ W2, const float* __restrict__ b2,
                           float* __restrict__ out) {
    __shared__ float p[64], z1[64], z2[10];
    int g = blockIdx.x, t = threadIdx.x;
    int s0 = g_nodeptr[g], s1 = g_nodeptr[g + 1];
    float acc = 0.f;
    for (int i = s0; i < s1; i++) acc += g_h1[i * 64 + t];   // h3 lives in g_h1
    p[t] = acc / fmaxf((float)(s1 - s0), 1.f);
    __syncthreads();
    float a1 = b1[t];
    for (int k = 0; k < 64; k++) a1 += p[k] * W1[k * 64 + t];
    z1[t] = fmaxf(a1, 0.f);
    __syncthreads();
    if (t < NC) {
        float a2 = b2[t];
        for (int k = 0; k < 64; k++) a2 += z1[k] * W2[k * 10 + t];
        z2[t] = a2;
    }
    __syncthreads();
    if (t == 0) {
        float mx = z2[0];
        for (int c = 1; c < NC; c++) mx = fmaxf(mx, z2[c]);
        float se = 0.f;
        for (int c = 0; c < NC; c++) se += expf(z2[c] - mx);
        float lse = mx + logf(se);
        for (int c = 0; c < NC; c++) out[g * NC + c] = z2[c] - lse;
    }
}

// ---------------- launcher ----------------
extern "C" void kernel_launch(void* const* d_in, const int* in_sizes, int n_in,
                              void* d_out, int out_size) {
    const float* x   = (const float*)d_in[0];
    const int*   ei  = (const int*)d_in[1];
    const int*   bat = (const int*)d_in[2];
    const float* W1l = (const float*)d_in[3];
    const float* b1l = (const float*)d_in[4];
    const float* W1r = (const float*)d_in[5];
    const float* W2l = (const float*)d_in[6];
    const float* b2l = (const float*)d_in[7];
    const float* W2r = (const float*)d_in[8];
    const float* W3l = (const float*)d_in[9];
    const float* b3l = (const float*)d_in[10];
    const float* W3r = (const float*)d_in[11];
    const float* Wl1 = (const float*)d_in[12];
    const float* bl1 = (const float*)d_in[13];
    const float* Wl2 = (const float*)d_in[14];
    const float* bl2 = (const float*)d_in[15];
    const int* src = ei;
    const int* dst = ei + NE;
    float* out_logits  = (float*)d_out;
    float* out_sampled = (float*)d_out + NG * NC;

    float *p_h1, *p_h2;
    cudaGetSymbolAddress((void**)&p_h1, g_h1);
    cudaGetSymbolAddress((void**)&p_h2, g_h2);

    cudaFuncSetAttribute((const void*)k_gemm<128>,
                         cudaFuncAttributeMaxDynamicSharedMemorySize, SMEM_G128);
    cudaFuncSetAttribute((const void*)k_gemm<64>,
                         cudaFuncAttributeMaxDynamicSharedMemorySize, SMEM_G64);
    cudaFuncSetAttribute((const void*)k_topk,
                         cudaFuncAttributeMaxDynamicSharedMemorySize, SMEM_TOPK);

    // graph structure (recomputed each call; deterministic result)
    k_zero<<<196, 256>>>();                                     // 1
    k_hist<<<(NE + 255) / 256, 256>>>(src, dst, bat);           // 2
    k_scan_block<<<NB_SCAN, 1024>>>();                          // 3
    k_gemm<128><<<(NN + 63) / 64, 256, SMEM_G128>>>(x, W1l, W1r); // 4  <- ncu slot
    k_scan_small<<<1, 1024>>>();                                // 5
    k_scan_addcur<<<196, 256>>>();                              // 6
    k_scatter<<<(NE + 255) / 256, 256>>>(src, dst);             // 7
    k_sortadj<<<(NN * 32 + 255) / 256, 256>>>();                // 8

    // layer 1 aggregation
    k_agg<false><<<(NN * 32 + 255) / 256, 256>>>(b1l, p_h1);    // 9

    // edge scores + per-graph top-k
    k_score<<<(NE + 31) / 32, 256>>>(src, dst, bat);            // 10
    k_gemm<64><<<(NN + 63) / 64, 256, SMEM_G64>>>(p_h1, W2l, W2r); // 11 (indep of topk)
    k_topk<<<NG, 512, SMEM_TOPK>>>(out_sampled);                // 12

    // layer 2
    k_agg<true><<<(NN * 32 + 255) / 256, 256>>>(b2l, p_h2);     // 13

    // layer 3 (h3 -> g_h1)
    k_gemm<64><<<(NN + 63) / 64, 256, SMEM_G64>>>(p_h2, W3l, W3r); // 14
    k_agg<true><<<(NN * 32 + 255) / 256, 256>>>(b3l, p_h1);     // 15

    // pooling + head
    k_poolhead<<<NG, 64>>>(Wl1, bl1, Wl2, bl2, out_logits);     // 16
}

// round 3
// speedup vs baseline: 1.1156x; 1.0855x over previous
#include <cuda_runtime.h>

#define NN 50000
#define NE 800000
#define FDIM 128
#define HDIM 64
#define NG 512
#define NC 10
#define NB_SCAN ((NN + 1023) / 1024)   /* 49 */

#define SMEM_G128 ((128*128 + 128*68) * 4)  /* 100352 */
#define SMEM_G64  ((64*128  + 64*68)  * 4)  /* 50176  */
#define SMEM_TOPK (8192 * 8)                /* 65536  */

typedef unsigned long long ull;

// ---------------- scratch (static device globals; no runtime alloc) ----------
__device__ float g_yl[NN * 64];          // GEMM left output (gathered randomly)
__device__ float g_yr[NN * 64];          // GEMM right output (streamed)
__device__ float g_h1[NN * 64];          // h1, later reused for h3
__device__ float g_h2[NN * 64];
__device__ float g_scores[NE];
__device__ float g_ew[NE];
__device__ ull g_buckets[NE];
__device__ ull g_adj[NE];                // (eid<<32)|src, CSR by dst
__device__ int g_deg[NN];
__device__ int g_rowptr[NN + 1];
__device__ int g_cursor[NN];
__device__ int g_part[64];
__device__ int g_segcnt[NG];
__device__ int g_segptr[NG + 1];
__device__ int g_segcur[NG];
__device__ int g_nodecnt[NG];
__device__ int g_nodeptr[NG + 1];

// ---------------- f32x2 helpers (FFMA2 path, sm_10x) ----------------
__device__ __forceinline__ ull dup2(float x) {
    ull r; unsigned u = __float_as_uint(x);
    asm("mov.b64 %0, {%1, %1};" : "=l"(r) : "r"(u));
    return r;
}
__device__ __forceinline__ void fma2(ull& d, ull a, ull b) {
    asm("fma.rn.f32x2 %0, %1, %2, %0;" : "+l"(d) : "l"(a), "l"(b));
}
__device__ __forceinline__ float2 unpk(ull v) {
    unsigned lo, hi;
    asm("mov.b64 {%0, %1}, %2;" : "=r"(lo), "=r"(hi) : "l"(v));
    return make_float2(__uint_as_float(lo), __uint_as_float(hi));
}

// ---------------- init / histogram ----------------
__global__ void k_zero() {
    int i = blockIdx.x * blockDim.x + threadIdx.x;
    if (i < NN) g_deg[i] = 0;
    if (i < NG) { g_segcnt[i] = 0; g_nodecnt[i] = 0; }
}

__global__ void k_hist(const int* __restrict__ src, const int* __restrict__ dst,
                       const int* __restrict__ batch) {
    int i = blockIdx.x * blockDim.x + threadIdx.x;
    if (i < NE) {
        atomicAdd(&g_deg[dst[i]], 1);
        atomicAdd(&g_segcnt[batch[src[i]]], 1);
    }
    if (i < NN) atomicAdd(&g_nodecnt[batch[i]], 1);
}

// ---------------- scans ----------------
__global__ void k_scan_block() {
    __shared__ int s[1024];
    int t = threadIdx.x;
    int i = blockIdx.x * 1024 + t;
    int v = (i < NN) ? g_deg[i] : 0;
    s[t] = v; __syncthreads();
    for (int off = 1; off < 1024; off <<= 1) {
        int a = (t >= off) ? s[t - off] : 0; __syncthreads();
        s[t] += a; __syncthreads();
    }
    if (i < NN) g_rowptr[i + 1] = s[t];
    if (t == 1023) g_part[blockIdx.x] = s[1023];
}

__device__ __forceinline__ int blk_scan_inc(int v, int* s) {
    int t = threadIdx.x;
    s[t] = v; __syncthreads();
    for (int off = 1; off < 1024; off <<= 1) {
        int a = (t >= off) ? s[t - off] : 0; __syncthreads();
        s[t] += a; __syncthreads();
    }
    int r = s[t]; __syncthreads();
    return r;
}

__global__ void k_scan_small() {
    __shared__ int s[1024];
    int t = threadIdx.x;
    int v = (t < NB_SCAN) ? g_part[t] : 0;
    int inc = blk_scan_inc(v, s);
    if (t < NB_SCAN) g_part[t] = inc - v;             // exclusive

    v = (t < NG) ? g_segcnt[t] : 0;
    inc = blk_scan_inc(v, s);
    if (t < NG) { g_segptr[t + 1] = inc; g_segcur[t] = inc - v; }
    if (t == 0) g_segptr[0] = 0;

    v = (t < NG) ? g_nodecnt[t] : 0;
    inc = blk_scan_inc(v, s);
    if (t < NG) g_nodeptr[t + 1] = inc;
    if (t == 0) g_nodeptr[0] = 0;
}

__global__ void k_scan_addcur() {
    int i = blockIdx.x * blockDim.x + threadIdx.x;
    if (i < NN) {
        int v = g_rowptr[i + 1] + g_part[i >> 10];
        g_rowptr[i + 1] = v;
        if (i + 1 < NN) g_cursor[i + 1] = v;
    }
    if (i == 0) { g_rowptr[0] = 0; g_cursor[0] = 0; }
}

// ---------------- CSR build (counting sort by dst) ----------------
__global__ void k_scatter(const int* __restrict__ src, const int* __restrict__ dst) {
    int e = blockIdx.x * blockDim.x + threadIdx.x;
    if (e >= NE) return;
    int p = atomicAdd(&g_cursor[dst[e]], 1);
    g_adj[p] = ((ull)(unsigned)e << 32) | (unsigned)src[e];
}

// stabilize per-dst edge order by edge id (determinism of fp add order)
__global__ void k_sortadj() {
    __shared__ ull buf[8][128];
    int w = (blockIdx.x * blockDim.x + threadIdx.x) >> 5;
    int lane = threadIdx.x & 31;
    int lw = threadIdx.x >> 5;
    if (w >= NN) return;
    int s0 = g_rowptr[w];
    int cnt = g_rowptr[w + 1] - s0;
    if (cnt <= 1 || cnt > 128) return;
    ull* b = buf[lw];
    for (int i = lane; i < cnt; i += 32) b[i] = g_adj[s0 + i];
    __syncwarp();
    for (int p = 0; p < cnt; p++) {
        for (int l = (p & 1) + 2 * lane; l + 1 < cnt; l += 64) {
            ull a = b[l], c = b[l + 1];
            if (a > c) { b[l] = c; b[l + 1] = a; }
        }
        __syncwarp();
    }
    for (int i = lane; i < cnt; i += 32) g_adj[s0 + i] = b[i];
}

// ---------------- GEMM: [yl | yr] = A[N,K] @ [Wa | Wb] (Wa,Wb each K x 64) ----
// 256 threads = 16x16; thread (tx,ty) owns rows ty*4..+3, cols tx*4..+3 of BOTH halves.
// Ws LDS.128 lane stride = 16B -> conflict-free. Mainloop uses packed fma.rn.f32x2.
template<int K>
__global__ __launch_bounds__(256) void k_gemm(const float* __restrict__ A,
                                              const float* __restrict__ Wa,
                                              const float* __restrict__ Wb) {
    extern __shared__ float sm[];
    float* Ws = sm;             // K * 128  (cols 0..63 = Wa, 64..127 = Wb)
    float* As = sm + K * 128;   // K * 68 (padded, transposed)
    int tid = threadIdx.x;
    for (int idx = tid; idx < K * 64; idx += 256) {
        int k = idx >> 6, c = idx & 63;
        Ws[k * 128 + c] = Wa[idx];
        Ws[k * 128 + 64 + c] = Wb[idx];
    }
    int row0 = blockIdx.x * 64;
    for (int idx = tid; idx < 64 * K; idx += 256) {
        int r = idx / K, k = idx - r * K;
        int row = row0 + r;
        As[k * 68 + r] = (row < NN) ? A[row * K + k] : 0.f;
    }
    __syncthreads();
    int tx = tid & 15, ty = tid >> 4;
    ull accL[4][2], accR[4][2];
#pragma unroll
    for (int i = 0; i < 4; i++) {
        accL[i][0] = 0ull; accL[i][1] = 0ull;
        accR[i][0] = 0ull; accR[i][1] = 0ull;
    }

#pragma unroll 8
    for (int k = 0; k < K; k++) {
        float4 a = *(const float4*)&As[k * 68 + ty * 4];
        ulonglong2 wl = *(const ulonglong2*)&Ws[k * 128 + tx * 4];
        ulonglong2 wr = *(const ulonglong2*)&Ws[k * 128 + 64 + tx * 4];
        ull a0 = dup2(a.x), a1 = dup2(a.y), a2 = dup2(a.z), a3 = dup2(a.w);
        fma2(accL[0][0], a0, wl.x); fma2(accL[0][1], a0, wl.y);
        fma2(accR[0][0], a0, wr.x); fma2(accR[0][1], a0, wr.y);
        fma2(accL[1][0], a1, wl.x); fma2(accL[1][1], a1, wl.y);
        fma2(accR[1][0], a1, wr.x); fma2(accR[1][1], a1, wr.y);
        fma2(accL[2][0], a2, wl.x); fma2(accL[2][1], a2, wl.y);
        fma2(accR[2][0], a2, wr.x); fma2(accR[2][1], a2, wr.y);
        fma2(accL[3][0], a3, wl.x); fma2(accL[3][1], a3, wl.y);
        fma2(accR[3][0], a3, wr.x); fma2(accR[3][1], a3, wr.y);
    }
#pragma unroll
    for (int i = 0; i < 4; i++) {
        int row = row0 + ty * 4 + i;
        if (row < NN) {
            float2 l0 = unpk(accL[i][0]), l1 = unpk(accL[i][1]);
            float2 r0 = unpk(accR[i][0]), r1 = unpk(accR[i][1]);
            *(float4*)&g_yl[row * 64 + tx * 4] = make_float4(l0.x, l0.y, l1.x, l1.y);
            *(float4*)&g_yr[row * 64 + tx * 4] = make_float4(r0.x, r0.y, r1.x, r1.y);
        }
    }
}

// ---------------- segment aggregation (warp per dst node, half-warp per edge) -
template<bool WEIGHTED>
__global__ void k_agg(const float* __restrict__ bias, float* __restrict__ hout) {
    int w = (blockIdx.x * blockDim.x + threadIdx.x) >> 5;
    int lane = threadIdx.x & 31;
    if (w >= NN) return;
    int grp = lane >> 4, sub = lane & 15;
    int s0 = g_rowptr[w], s1 = g_rowptr[w + 1];
    float4 acc = make_float4(0.f, 0.f, 0.f, 0.f);
    for (int p = s0 + grp; p < s1; p += 2) {
        ull ad = __ldg(&g_adj[p]);                      // broadcast within half-warp
        int src = (int)(unsigned)ad;
        float wg;
        if (WEIGHTED) {
            wg = __ldg(&g_ew[(int)(ad >> 32)]);
            if (wg == 0.f) continue;                    // half-warp-uniform skip
        }
        float4 v = *(const float4*)&g_yl[src * 64 + sub * 4];
        if (WEIGHTED) {
            acc.x += wg * v.x; acc.y += wg * v.y; acc.z += wg * v.z; acc.w += wg * v.w;
        } else {
            acc.x += v.x; acc.y += v.y; acc.z += v.z; acc.w += v.w;
        }
    }
    acc.x += __shfl_xor_sync(0xffffffffu, acc.x, 16);
    acc.y += __shfl_xor_sync(0xffffffffu, acc.y, 16);
    acc.z += __shfl_xor_sync(0xffffffffu, acc.z, 16);
    acc.w += __shfl_xor_sync(0xffffffffu, acc.w, 16);
    if (grp == 0) {
        float dg = fmaxf((float)(s1 - s0), 1.f);
        int c = sub * 4;
        float4 b  = *(const float4*)&bias[c];
        float4 yr = *(const float4*)&g_yr[w * 64 + c];
        float4 o;
        o.x = fmaxf(acc.x / dg + b.x + yr.x, 0.f);
        o.y = fmaxf(acc.y / dg + b.y + yr.y, 0.f);
        o.z = fmaxf(acc.z / dg + b.z + yr.z, 0.f);
        o.w = fmaxf(acc.w / dg + b.w + yr.w, 0.f);
        *(float4*)&hout[w * 64 + c] = o;
    }
}

// ---------------- edge scores via dst-CSR (h1[dst] register-stationary) -------
__global__ void k_score(const int* __restrict__ batch) {
    int w = (blockIdx.x * blockDim.x + threadIdx.x) >> 5;
    int lane = threadIdx.x & 31;
    if (w >= NN) return;
    int grp = lane >> 4, sub = lane & 15;
    unsigned hmask = 0xFFFFu << (grp * 16);
    int s0 = g_rowptr[w], s1 = g_rowptr[w + 1];
    float4 hd = *(const float4*)&g_h1[w * 64 + sub * 4];
    for (int p = s0 + grp; p < s1; p += 2) {
        ull ad = __ldg(&g_adj[p]);
        int src = (int)(unsigned)ad;
        int eid = (int)(ad >> 32);
        float4 hs = *(const float4*)&g_h1[src * 64 + sub * 4];
        float v = hs.x * hd.x + hs.y * hd.y + hs.z * hd.z + hs.w * hd.w;
        v += __shfl_xor_sync(hmask, v, 1);
        v += __shfl_xor_sync(hmask, v, 2);
        v += __shfl_xor_sync(hmask, v, 4);
        v += __shfl_xor_sync(hmask, v, 8);
        if (sub == 0) {
            g_scores[eid] = v;
            unsigned u = __float_as_uint(v);
            u = (u & 0x80000000u) ? ~u : (u | 0x80000000u);
            ull key = ((ull)u << 32) | (unsigned)(~(unsigned)eid);
            int g = __ldg(&batch[src]);
            int pp = atomicAdd(&g_segcur[g], 1);
            g_buckets[pp] = key;
        }
    }
}

// ---------------- per-graph exact top-k (bitonic sort of (score, eid) keys) ---
__global__ void k_topk(float* __restrict__ sampled) {
    extern __shared__ ull sk[];
    int g = blockIdx.x;
    int s0 = g_segptr[g];
    int n = g_segptr[g + 1] - s0;
    if (n <= 0) return;
    int m = 1;
    while (m < n) m <<= 1;
    if (m > 8192) m = 8192;           // safety; never hit for this data
    int nn2 = min(n, m);
    for (int i = threadIdx.x; i < m; i += blockDim.x)
        sk[i] = (i < nn2) ? g_buckets[s0 + i] : 0ull;
    __syncthreads();
    for (int k2 = 2; k2 <= m; k2 <<= 1) {
        for (int jj = k2 >> 1; jj > 0; jj >>= 1) {
            for (int i = threadIdx.x; i < m; i += blockDim.x) {
                int ij = i ^ jj;
                if (ij > i) {
                    ull a = sk[i], b = sk[ij];
                    bool desc = ((i & k2) == 0);
                    if (desc ? (a < b) : (a > b)) { sk[i] = b; sk[ij] = a; }
                }
            }
            __syncthreads();
        }
    }
    int k = (n + 1) >> 1;             // ceil(0.5 * n)
    for (int i = threadIdx.x; i < nn2; i += blockDim.x) {
        unsigned eid = ~(unsigned)(sk[i] & 0xffffffffu);
        float sel = (i < k) ? 1.f : 0.f;
        sampled[eid] = sel;
        g_ew[eid] = sel * g_scores[eid];
    }
}

// ---------------- pooling + MLP head (fused) ----------------
__global__ void k_poolhead(const float* __restrict__ W1, const float* __restrict__ b1,
                           const float* __restrict__ W2, const float* __restrict__ b2,
                           float* __restrict__ out) {
    __shared__ float p[64], z1[64], z2[10];
    int g = blockIdx.x, t = threadIdx.x;
    int s0 = g_nodeptr[g], s1 = g_nodeptr[g + 1];
    float acc = 0.f;
    for (int i = s0; i < s1; i++) acc += g_h1[i * 64 + t];   // h3 lives in g_h1
    p[t] = acc / fmaxf((float)(s1 - s0), 1.f);
    __syncthreads();
    float a1 = b1[t];
    for (int k = 0; k < 64; k++) a1 += p[k] * W1[k * 64 + t];
    z1[t] = fmaxf(a1, 0.f);
    __syncthreads();
    if (t < NC) {
        float a2 = b2[t];
        for (int k = 0; k < 64; k++) a2 += z1[k] * W2[k * 10 + t];
        z2[t] = a2;
    }
    __syncthreads();
    if (t == 0) {
        float mx = z2[0];
        for (int c = 1; c < NC; c++) mx = fmaxf(mx, z2[c]);
        float se = 0.f;
        for (int c = 0; c < NC; c++) se += expf(z2[c] - mx);
        float lse = mx + logf(se);
        for (int c = 0; c < NC; c++) out[g * NC + c] = z2[c] - lse;
    }
}

// ---------------- launcher ----------------
extern "C" void kernel_launch(void* const* d_in, const int* in_sizes, int n_in,
                              void* d_out, int out_size) {
    const float* x   = (const float*)d_in[0];
    const int*   ei  = (const int*)d_in[1];
    const int*   bat = (const int*)d_in[2];
    const float* W1l = (const float*)d_in[3];
    const float* b1l = (const float*)d_in[4];
    const float* W1r = (const float*)d_in[5];
    const float* W2l = (const float*)d_in[6];
    const float* b2l = (const float*)d_in[7];
    const float* W2r = (const float*)d_in[8];
    const float* W3l = (const float*)d_in[9];
    const float* b3l = (const float*)d_in[10];
    const float* W3r = (const float*)d_in[11];
    const float* Wl1 = (const float*)d_in[12];
    const float* bl1 = (const float*)d_in[13];
    const float* Wl2 = (const float*)d_in[14];
    const float* bl2 = (const float*)d_in[15];
    const int* src = ei;
    const int* dst = ei + NE;
    float* out_logits  = (float*)d_out;
    float* out_sampled = (float*)d_out + NG * NC;

    float *p_h1, *p_h2;
    cudaGetSymbolAddress((void**)&p_h1, g_h1);
    cudaGetSymbolAddress((void**)&p_h2, g_h2);

    cudaFuncSetAttribute((const void*)k_gemm<128>,
                         cudaFuncAttributeMaxDynamicSharedMemorySize, SMEM_G128);
    cudaFuncSetAttribute((const void*)k_gemm<64>,
                         cudaFuncAttributeMaxDynamicSharedMemorySize, SMEM_G64);
    cudaFuncSetAttribute((const void*)k_topk,
                         cudaFuncAttributeMaxDynamicSharedMemorySize, SMEM_TOPK);

    // graph structure (recomputed each call; deterministic result)
    k_zero<<<196, 256>>>();                                     // 1
    k_hist<<<(NE + 255) / 256, 256>>>(src, dst, bat);           // 2
    k_scan_block<<<NB_SCAN, 1024>>>();                          // 3
    k_gemm<128><<<(NN + 63) / 64, 256, SMEM_G128>>>(x, W1l, W1r); // 4  <- ncu slot
    k_scan_small<<<1, 1024>>>();                                // 5
    k_scan_addcur<<<196, 256>>>();                              // 6
    k_scatter<<<(NE + 255) / 256, 256>>>(src, dst);             // 7
    k_sortadj<<<(NN * 32 + 255) / 256, 256>>>();                // 8

    // layer 1 aggregation
    k_agg<false><<<(NN * 32 + 255) / 256, 256>>>(b1l, p_h1);    // 9

    // edge scores + per-graph top-k
    k_score<<<(NN * 32 + 255) / 256, 256>>>(bat);               // 10
    k_gemm<64><<<(NN + 63) / 64, 256, SMEM_G64>>>(p_h1, W2l, W2r); // 11 (indep of topk)
    k_topk<<<NG, 512, SMEM_TOPK>>>(out_sampled);                // 12

    // layer 2
    k_agg<true><<<(NN * 32 + 255) / 256, 256>>>(b2l, p_h2);     // 13

    // layer 3 (h3 -> g_h1)
    k_gemm<64><<<(NN + 63) / 64, 256, SMEM_G64>>>(p_h2, W3l, W3r); // 14
    k_agg<true><<<(NN * 32 + 255) / 256, 256>>>(b3l, p_h1);     // 15

    // pooling + head
    k_poolhead<<<NG, 64>>>(Wl1, bl1, Wl2, bl2, out_logits);     // 16
}

// round 5
// speedup vs baseline: 1.1720x; 1.0506x over previous
#include <cuda_runtime.h>

#define NN 50000
#define NE 800000
#define FDIM 128
#define HDIM 64
#define NG 512
#define NC 10
#define NB_SCAN ((NN + 1023) / 1024)   /* 49 */

#define APAD 136
#define SMEM_G128 ((128*128 + 128*APAD) * 4)  /* 135168 */
#define SMEM_G64  ((64*128  + 64*APAD)  * 4)  /* 67584  */
#define SMEM_TOPK (8192 * 8)                  /* 65536  */

typedef unsigned long long ull;

// ---------------- scratch (static device globals; no runtime alloc) ----------
__device__ float g_yl[NN * 64];          // GEMM left output (gathered randomly)
__device__ float g_yr[NN * 64];          // GEMM right output (streamed)
__device__ float g_h1[NN * 64];          // h1, later reused for h3
__device__ float g_h2[NN * 64];
__device__ float g_scores[NE];
__device__ float g_ew[NE];
__device__ ull g_buckets[NE];
__device__ ull g_adj[NE];                // (eid<<32)|src, CSR by dst
__device__ int g_deg[NN];
__device__ int g_rowptr[NN + 1];
__device__ int g_cursor[NN];
__device__ int g_part[64];
__device__ int g_segcnt[NG];
__device__ int g_segptr[NG + 1];
__device__ int g_segcur[NG];
__device__ int g_nodecnt[NG];
__device__ int g_nodeptr[NG + 1];

// ---------------- f32x2 helpers (FFMA2 path, sm_10x) ----------------
__device__ __forceinline__ ull dup2(float x) {
    ull r; unsigned u = __float_as_uint(x);
    asm("mov.b64 %0, {%1, %1};" : "=l"(r) : "r"(u));
    return r;
}
__device__ __forceinline__ void fma2(ull& d, ull a, ull b) {
    asm("fma.rn.f32x2 %0, %1, %2, %0;" : "+l"(d) : "l"(a), "l"(b));
}
__device__ __forceinline__ float2 unpk(ull v) {
    unsigned lo, hi;
    asm("mov.b64 {%0, %1}, %2;" : "=r"(lo), "=r"(hi) : "l"(v));
    return make_float2(__uint_as_float(lo), __uint_as_float(hi));
}

// ---------------- init / histogram ----------------
__global__ void k_zero() {
    int i = blockIdx.x * blockDim.x + threadIdx.x;
    if (i < NN) g_deg[i] = 0;
    if (i < NG) { g_segcnt[i] = 0; g_nodecnt[i] = 0; }
}

__global__ void k_hist(const int* __restrict__ src, const int* __restrict__ dst,
                       const int* __restrict__ batch) {
    int i = blockIdx.x * blockDim.x + threadIdx.x;
    if (i < NE) {
        atomicAdd(&g_deg[dst[i]], 1);
        atomicAdd(&g_segcnt[batch[src[i]]], 1);
    }
    if (i < NN) atomicAdd(&g_nodecnt[batch[i]], 1);
}

// ---------------- scans ----------------
__global__ void k_scan_block() {
    __shared__ int s[1024];
    int t = threadIdx.x;
    int i = blockIdx.x * 1024 + t;
    int v = (i < NN) ? g_deg[i] : 0;
    s[t] = v; __syncthreads();
    for (int off = 1; off < 1024; off <<= 1) {
        int a = (t >= off) ? s[t - off] : 0; __syncthreads();
        s[t] += a; __syncthreads();
    }
    if (i < NN) g_rowptr[i + 1] = s[t];
    if (t == 1023) g_part[blockIdx.x] = s[1023];
}

__device__ __forceinline__ int blk_scan_inc(int v, int* s) {
    int t = threadIdx.x;
    s[t] = v; __syncthreads();
    for (int off = 1; off < 1024; off <<= 1) {
        int a = (t >= off) ? s[t - off] : 0; __syncthreads();
        s[t] += a; __syncthreads();
    }
    int r = s[t]; __syncthreads();
    return r;
}

__global__ void k_scan_small() {
    __shared__ int s[1024];
    int t = threadIdx.x;
    int v = (t < NB_SCAN) ? g_part[t] : 0;
    int inc = blk_scan_inc(v, s);
    if (t < NB_SCAN) g_part[t] = inc - v;             // exclusive

    v = (t < NG) ? g_segcnt[t] : 0;
    inc = blk_scan_inc(v, s);
    if (t < NG) { g_segptr[t + 1] = inc; g_segcur[t] = inc - v; }
    if (t == 0) g_segptr[0] = 0;

    v = (t < NG) ? g_nodecnt[t] : 0;
    inc = blk_scan_inc(v, s);
    if (t < NG) g_nodeptr[t + 1] = inc;
    if (t == 0) g_nodeptr[0] = 0;
}

__global__ void k_scan_addcur() {
    int i = blockIdx.x * blockDim.x + threadIdx.x;
    if (i < NN) {
        int v = g_rowptr[i + 1] + g_part[i >> 10];
        g_rowptr[i + 1] = v;
        if (i + 1 < NN) g_cursor[i + 1] = v;
    }
    if (i == 0) { g_rowptr[0] = 0; g_cursor[0] = 0; }
}

// ---------------- CSR build (counting sort by dst) ----------------
__global__ void k_scatter(const int* __restrict__ src, const int* __restrict__ dst) {
    int e = blockIdx.x * blockDim.x + threadIdx.x;
    if (e >= NE) return;
    int p = atomicAdd(&g_cursor[dst[e]], 1);
    g_adj[p] = ((ull)(unsigned)e << 32) | (unsigned)src[e];
}

// stabilize per-dst edge order by edge id (determinism of fp add order)
__global__ void k_sortadj() {
    __shared__ ull buf[8][128];
    int w = (blockIdx.x * blockDim.x + threadIdx.x) >> 5;
    int lane = threadIdx.x & 31;
    int lw = threadIdx.x >> 5;
    if (w >= NN) return;
    int s0 = g_rowptr[w];
    int cnt = g_rowptr[w + 1] - s0;
    if (cnt <= 1 || cnt > 128) return;
    ull* b = buf[lw];
    for (int i = lane; i < cnt; i += 32) b[i] = g_adj[s0 + i];
    __syncwarp();
    for (int p = 0; p < cnt; p++) {
        for (int l = (p & 1) + 2 * lane; l + 1 < cnt; l += 64) {
            ull a = b[l], c = b[l + 1];
            if (a > c) { b[l] = c; b[l + 1] = a; }
        }
        __syncwarp();
    }
    for (int i = lane; i < cnt; i += 32) g_adj[s0 + i] = b[i];
}

// ---------------- GEMM: [yl | yr] = A[N,K] @ [Wa | Wb] (Wa,Wb each K x 64) ----
// 128-row tile, 256 threads; thread (tx,ty) owns rows ty*8..+7, cols tx*4..+3 of
// both halves. LDS and FFMA2 issue balanced at 128 cyc/block/k.
template<int K>
__global__ __launch_bounds__(256) void k_gemm(const float* __restrict__ A,
                                              const float* __restrict__ Wa,
                                              const float* __restrict__ Wb) {
    extern __shared__ float sm[];
    float* Ws = sm;             // K * 128  (cols 0..63 = Wa, 64..127 = Wb)
    float* As = sm + K * 128;   // K * APAD (16B-aligned rows, transposed)
    int tid = threadIdx.x;
    for (int idx = tid; idx < K * 64; idx += 256) {
        int k = idx >> 6, c = idx & 63;
        Ws[k * 128 + c] = Wa[idx];
        Ws[k * 128 + 64 + c] = Wb[idx];
    }
    int row0 = blockIdx.x * 128;
    for (int idx = tid; idx < 128 * K; idx += 256) {
        int r = idx / K, k = idx - r * K;
        int row = row0 + r;
        As[k * APAD + r] = (row < NN) ? A[row * K + k] : 0.f;
    }
    __syncthreads();
    int tx = tid & 15, ty = tid >> 4;
    ull accL[8][2], accR[8][2];
#pragma unroll
    for (int i = 0; i < 8; i++) {
        accL[i][0] = 0ull; accL[i][1] = 0ull;
        accR[i][0] = 0ull; accR[i][1] = 0ull;
    }

#pragma unroll 2
    for (int k = 0; k < K; k++) {
        float4 aLo = *(const float4*)&As[k * APAD + ty * 8];
        float4 aHi = *(const float4*)&As[k * APAD + ty * 8 + 4];
        ulonglong2 wl = *(const ulonglong2*)&Ws[k * 128 + tx * 4];
        ulonglong2 wr = *(const ulonglong2*)&Ws[k * 128 + 64 + tx * 4];
        float ar[8] = {aLo.x, aLo.y, aLo.z, aLo.w, aHi.x, aHi.y, aHi.z, aHi.w};
#pragma unroll
        for (int i = 0; i < 8; i++) {
            ull ai = dup2(ar[i]);
            fma2(accL[i][0], ai, wl.x); fma2(accL[i][1], ai, wl.y);
            fma2(accR[i][0], ai, wr.x); fma2(accR[i][1], ai, wr.y);
        }
    }
#pragma unroll
    for (int i = 0; i < 8; i++) {
        int row = row0 + ty * 8 + i;
        if (row < NN) {
            float2 l0 = unpk(accL[i][0]), l1 = unpk(accL[i][1]);
            float2 r0 = unpk(accR[i][0]), r1 = unpk(accR[i][1]);
            *(float4*)&g_yl[row * 64 + tx * 4] = make_float4(l0.x, l0.y, l1.x, l1.y);
            *(float4*)&g_yr[row * 64 + tx * 4] = make_float4(r0.x, r0.y, r1.x, r1.y);
        }
    }
}

// ---------------- segment aggregation (warp per dst node, half-warp per edge) -
template<bool WEIGHTED>
__global__ void k_agg(const float* __restrict__ bias, float* __restrict__ hout) {
    int w = (blockIdx.x * blockDim.x + threadIdx.x) >> 5;
    int lane = threadIdx.x & 31;
    if (w >= NN) return;
    int grp = lane >> 4, sub = lane & 15;
    int s0 = g_rowptr[w], s1 = g_rowptr[w + 1];
    float4 acc = make_float4(0.f, 0.f, 0.f, 0.f);
    for (int p = s0 + grp; p < s1; p += 2) {
        ull ad = __ldg(&g_adj[p]);                      // broadcast within half-warp
        int src = (int)(unsigned)ad;
        float wg;
        if (WEIGHTED) {
            wg = __ldg(&g_ew[(int)(ad >> 32)]);
            if (wg == 0.f) continue;                    // half-warp-uniform skip
        }
        float4 v = *(const float4*)&g_yl[src * 64 + sub * 4];
        if (WEIGHTED) {
            acc.x += wg * v.x; acc.y += wg * v.y; acc.z += wg * v.z; acc.w += wg * v.w;
        } else {
            acc.x += v.x; acc.y += v.y; acc.z += v.z; acc.w += v.w;
        }
    }
    acc.x += __shfl_xor_sync(0xffffffffu, acc.x, 16);
    acc.y += __shfl_xor_sync(0xffffffffu, acc.y, 16);
    acc.z += __shfl_xor_sync(0xffffffffu, acc.z, 16);
    acc.w += __shfl_xor_sync(0xffffffffu, acc.w, 16);
    if (grp == 0) {
        float dg = fmaxf((float)(s1 - s0), 1.f);
        int c = sub * 4;
        float4 b  = *(const float4*)&bias[c];
        float4 yr = *(const float4*)&g_yr[w * 64 + c];
        float4 o;
        o.x = fmaxf(acc.x / dg + b.x + yr.x, 0.f);
        o.y = fmaxf(acc.y / dg + b.y + yr.y, 0.f);
        o.z = fmaxf(acc.z / dg + b.z + yr.z, 0.f);
        o.w = fmaxf(acc.w / dg + b.w + yr.w, 0.f);
        *(float4*)&hout[w * 64 + c] = o;
    }
}

// ---------------- edge scores via dst-CSR (h1[dst] register-stationary) -------
__global__ void k_score(const int* __restrict__ batch) {
    int w = (blockIdx.x * blockDim.x + threadIdx.x) >> 5;
    int lane = threadIdx.x & 31;
    if (w >= NN) return;
    int grp = lane >> 4, sub = lane & 15;
    unsigned hmask = 0xFFFFu << (grp * 16);
    int s0 = g_rowptr[w], s1 = g_rowptr[w + 1];
    float4 hd = *(const float4*)&g_h1[w * 64 + sub * 4];
    for (int p = s0 + grp; p < s1; p += 2) {
        ull ad = __ldg(&g_adj[p]);
        int src = (int)(unsigned)ad;
        int eid = (int)(ad >> 32);
        float4 hs = *(const float4*)&g_h1[src * 64 + sub * 4];
        float v = hs.x * hd.x + hs.y * hd.y + hs.z * hd.z + hs.w * hd.w;
        v += __shfl_xor_sync(hmask, v, 1);
        v += __shfl_xor_sync(hmask, v, 2);
        v += __shfl_xor_sync(hmask, v, 4);
        v += __shfl_xor_sync(hmask, v, 8);
        if (sub == 0) {
            g_scores[eid] = v;
            unsigned u = __float_as_uint(v);
            u = (u & 0x80000000u) ? ~u : (u | 0x80000000u);
            ull key = ((ull)u << 32) | (unsigned)(~(unsigned)eid);
            int g = __ldg(&batch[src]);
            int pp = atomicAdd(&g_segcur[g], 1);
            g_buckets[pp] = key;
        }
    }
}

// ---------------- per-graph exact top-k (bitonic sort of (score, eid) keys) ---
__global__ void k_topk(float* __restrict__ sampled) {
    extern __shared__ ull sk[];
    int g = blockIdx.x;
    int s0 = g_segptr[g];
    int n = g_segptr[g + 1] - s0;
    if (n <= 0) return;
    int m = 1;
    while (m < n) m <<= 1;
    if (m > 8192) m = 8192;           // safety; never hit for this data
    int nn2 = min(n, m);
    for (int i = threadIdx.x; i < m; i += blockDim.x)
        sk[i] = (i < nn2) ? g_buckets[s0 + i] : 0ull;
    __syncthreads();
    for (int k2 = 2; k2 <= m; k2 <<= 1) {
        for (int jj = k2 >> 1; jj > 0; jj >>= 1) {
            for (int i = threadIdx.x; i < m; i += blockDim.x) {
                int ij = i ^ jj;
                if (ij > i) {
                    ull a = sk[i], b = sk[ij];
                    bool desc = ((i & k2) == 0);
                    if (desc ? (a < b) : (a > b)) { sk[i] = b; sk[ij] = a; }
                }
            }
            __syncthreads();
        }
    }
    int k = (n + 1) >> 1;             // ceil(0.5 * n)
    for (int i = threadIdx.x; i < nn2; i += blockDim.x) {
        unsigned eid = ~(unsigned)(sk[i] & 0xffffffffu);
        float sel = (i < k) ? 1.f : 0.f;
        sampled[eid] = sel;
        g_ew[eid] = sel * g_scores[eid];
    }
}

// ---------------- pooling + MLP head (fused) ----------------
__global__ void k_poolhead(const float* __restrict__ W1, const float* __restrict__ b1,
                           const float* __restrict__ W2, const float* __restrict__ b2,
                           float* __restrict__ out) {
    __shared__ float p[64], z1[64], z2[10];
    int g = blockIdx.x, t = threadIdx.x;
    int s0 = g_nodeptr[g], s1 = g_nodeptr[g + 1];
    float acc = 0.f;
    for (int i = s0; i < s1; i++) acc += g_h1[i * 64 + t];   // h3 lives in g_h1
    p[t] = acc / fmaxf((float)(s1 - s0), 1.f);
    __syncthreads();
    float a1 = b1[t];
    for (int k = 0; k < 64; k++) a1 += p[k] * W1[k * 64 + t];
    z1[t] = fmaxf(a1, 0.f);
    __syncthreads();
    if (t < NC) {
        float a2 = b2[t];
        for (int k = 0; k < 64; k++) a2 += z1[k] * W2[k * 10 + t];
        z2[t] = a2;
    }
    __syncthreads();
    if (t == 0) {
        float mx = z2[0];
        for (int c = 1; c < NC; c++) mx = fmaxf(mx, z2[c]);
        float se = 0.f;
        for (int c = 0; c < NC; c++) se += expf(z2[c] - mx);
        float lse = mx + logf(se);
        for (int c = 0; c < NC; c++) out[g * NC + c] = z2[c] - lse;
    }
}

// ---------------- launcher ----------------
extern "C" void kernel_launch(void* const* d_in, const int* in_sizes, int n_in,
                              void* d_out, int out_size) {
    const float* x   = (const float*)d_in[0];
    const int*   ei  = (const int*)d_in[1];
    const int*   bat = (const int*)d_in[2];
    const float* W1l = (const float*)d_in[3];
    const float* b1l = (const float*)d_in[4];
    const float* W1r = (const float*)d_in[5];
    const float* W2l = (const float*)d_in[6];
    const float* b2l = (const float*)d_in[7];
    const float* W2r = (const float*)d_in[8];
    const float* W3l = (const float*)d_in[9];
    const float* b3l = (const float*)d_in[10];
    const float* W3r = (const float*)d_in[11];
    const float* Wl1 = (const float*)d_in[12];
    const float* bl1 = (const float*)d_in[13];
    const float* Wl2 = (const float*)d_in[14];
    const float* bl2 = (const float*)d_in[15];
    const int* src = ei;
    const int* dst = ei + NE;
    float* out_logits  = (float*)d_out;
    float* out_sampled = (float*)d_out + NG * NC;

    float *p_h1, *p_h2;
    cudaGetSymbolAddress((void**)&p_h1, g_h1);
    cudaGetSymbolAddress((void**)&p_h2, g_h2);

    cudaFuncSetAttribute((const void*)k_gemm<128>,
                         cudaFuncAttributeMaxDynamicSharedMemorySize, SMEM_G128);
    cudaFuncSetAttribute((const void*)k_gemm<64>,
                         cudaFuncAttributeMaxDynamicSharedMemorySize, SMEM_G64);
    cudaFuncSetAttribute((const void*)k_topk,
                         cudaFuncAttributeMaxDynamicSharedMemorySize, SMEM_TOPK);

    // side stream + events (created per call; capture-time only, replay uses graph)
    cudaStream_t s2;
    cudaStreamCreateWithFlags(&s2, cudaStreamNonBlocking);
    cudaEvent_t e0, e1, e2, e3;
    cudaEventCreateWithFlags(&e0, cudaEventDisableTiming);
    cudaEventCreateWithFlags(&e1, cudaEventDisableTiming);
    cudaEventCreateWithFlags(&e2, cudaEventDisableTiming);
    cudaEventCreateWithFlags(&e3, cudaEventDisableTiming);

    // ---- fork: structure build on s2, gemm128 on main ----
    cudaEventRecord(e0, 0);
    cudaStreamWaitEvent(s2, e0, 0);

    k_zero<<<196, 256, 0, s2>>>();                                  // 1
    k_hist<<<(NE + 255) / 256, 256, 0, s2>>>(src, dst, bat);        // 2
    k_scan_block<<<NB_SCAN, 1024, 0, s2>>>();                       // 3
    k_gemm<128><<<(NN + 127) / 128, 256, SMEM_G128>>>(x, W1l, W1r); // 4 (main)
    k_scan_small<<<1, 1024, 0, s2>>>();                             // 5
    k_scan_addcur<<<196, 256, 0, s2>>>();                           // 6
    k_scatter<<<(NE + 255) / 256, 256, 0, s2>>>(src, dst);          // 7
    k_sortadj<<<(NN * 32 + 255) / 256, 256, 0, s2>>>();             // 8

    cudaEventRecord(e1, s2);
    cudaStreamWaitEvent(0, e1, 0);      // join

    // layer 1 aggregation (needs gemm128 + CSR)
    k_agg<false><<<(NN * 32 + 255) / 256, 256>>>(b1l, p_h1);        // 9

    // ---- fork: layer-2 gemm on s2, score+topk on main ----
    cudaEventRecord(e2, 0);
    cudaStreamWaitEvent(s2, e2, 0);

    k_gemm<64><<<(NN + 127) / 128, 256, SMEM_G64, s2>>>(p_h1, W2l, W2r); // 10
    k_score<<<(NN * 32 + 255) / 256, 256>>>(bat);                   // 11
    k_topk<<<NG, 512, SMEM_TOPK>>>(out_sampled);                    // 12

    cudaEventRecord(e3, s2);
    cudaStreamWaitEvent(0, e3, 0);      // join

    // layer 2 aggregation
    k_agg<true><<<(NN * 32 + 255) / 256, 256>>>(b2l, p_h2);         // 13

    // layer 3 (h3 -> g_h1)
    k_gemm<64><<<(NN + 127) / 128, 256, SMEM_G64>>>(p_h2, W3l, W3r); // 14
    k_agg<true><<<(NN * 32 + 255) / 256, 256>>>(b3l, p_h1);         // 15

    // pooling + head
    k_poolhead<<<NG, 64>>>(Wl1, bl1, Wl2, bl2, out_logits);         // 16
}

// round 6
// speedup vs baseline: 1.1898x; 1.0151x over previous
#include <cuda_runtime.h>

#define NN 50000
#define NE 800000
#define FDIM 128
#define HDIM 64
#define NG 512
#define NC 10
#define NB_SCAN ((NN + 1023) / 1024)   /* 49 */

#define APAD 68
#define SMEM_G128 ((128*128 + 128*APAD) * 4)  /* 100352 */
#define SMEM_G64  ((64*128  + 64*APAD)  * 4)  /* 50176  */
#define SMEM_TOPK (8192 * 8)                  /* 65536  */

typedef unsigned long long ull;

// ---------------- scratch (static device globals; no runtime alloc) ----------
__device__ float g_yl[NN * 64];          // GEMM left output (gathered randomly)
__device__ float g_yr[NN * 64];          // GEMM right output (streamed)
__device__ float g_h1[NN * 64];          // h1, later reused for h3
__device__ float g_h2[NN * 64];
__device__ float g_scores[NE];
__device__ float g_ew[NE];
__device__ ull g_buckets[NE];
__device__ ull g_adj[NE];                // (eid<<32)|src, CSR by dst
__device__ int g_deg[NN];
__device__ int g_rowptr[NN + 1];
__device__ int g_cursor[NN];
__device__ int g_part[64];
__device__ int g_segcnt[NG];
__device__ int g_segptr[NG + 1];
__device__ int g_segcur[NG];
__device__ int g_nodecnt[NG];
__device__ int g_nodeptr[NG + 1];

// ---------------- f32x2 helpers (FFMA2 path, sm_10x) ----------------
__device__ __forceinline__ ull dup2(float x) {
    ull r; unsigned u = __float_as_uint(x);
    asm("mov.b64 %0, {%1, %1};" : "=l"(r) : "r"(u));
    return r;
}
__device__ __forceinline__ void fma2(ull& d, ull a, ull b) {
    asm("fma.rn.f32x2 %0, %1, %2, %0;" : "+l"(d) : "l"(a), "l"(b));
}
__device__ __forceinline__ float2 unpk(ull v) {
    unsigned lo, hi;
    asm("mov.b64 {%0, %1}, %2;" : "=r"(lo), "=r"(hi) : "l"(v));
    return make_float2(__uint_as_float(lo), __uint_as_float(hi));
}

// ---------------- init / histogram ----------------
__global__ void k_zero() {
    int i = blockIdx.x * blockDim.x + threadIdx.x;
    if (i < NN) g_deg[i] = 0;
    if (i < NG) { g_segcnt[i] = 0; g_nodecnt[i] = 0; }
}

__global__ void k_hist(const int* __restrict__ src, const int* __restrict__ dst,
                       const int* __restrict__ batch) {
    int i = blockIdx.x * blockDim.x + threadIdx.x;
    if (i < NE) {
        atomicAdd(&g_deg[dst[i]], 1);
        atomicAdd(&g_segcnt[batch[src[i]]], 1);
    }
    if (i < NN) atomicAdd(&g_nodecnt[batch[i]], 1);
}

// ---------------- scans ----------------
__global__ void k_scan_block() {
    __shared__ int s[1024];
    int t = threadIdx.x;
    int i = blockIdx.x * 1024 + t;
    int v = (i < NN) ? g_deg[i] : 0;
    s[t] = v; __syncthreads();
    for (int off = 1; off < 1024; off <<= 1) {
        int a = (t >= off) ? s[t - off] : 0; __syncthreads();
        s[t] += a; __syncthreads();
    }
    if (i < NN) g_rowptr[i + 1] = s[t];
    if (t == 1023) g_part[blockIdx.x] = s[1023];
}

__device__ __forceinline__ int blk_scan_inc(int v, int* s) {
    int t = threadIdx.x;
    s[t] = v; __syncthreads();
    for (int off = 1; off < 1024; off <<= 1) {
        int a = (t >= off) ? s[t - off] : 0; __syncthreads();
        s[t] += a; __syncthreads();
    }
    int r = s[t]; __syncthreads();
    return r;
}

__global__ void k_scan_small() {
    __shared__ int s[1024];
    int t = threadIdx.x;
    int v = (t < NB_SCAN) ? g_part[t] : 0;
    int inc = blk_scan_inc(v, s);
    if (t < NB_SCAN) g_part[t] = inc - v;             // exclusive

    v = (t < NG) ? g_segcnt[t] : 0;
    inc = blk_scan_inc(v, s);
    if (t < NG) { g_segptr[t + 1] = inc; g_segcur[t] = inc - v; }
    if (t == 0) g_segptr[0] = 0;

    v = (t < NG) ? g_nodecnt[t] : 0;
    inc = blk_scan_inc(v, s);
    if (t < NG) g_nodeptr[t + 1] = inc;
    if (t == 0) g_nodeptr[0] = 0;
}

__global__ void k_scan_addcur() {
    int i = blockIdx.x * blockDim.x + threadIdx.x;
    if (i < NN) {
        int v = g_rowptr[i + 1] + g_part[i >> 10];
        g_rowptr[i + 1] = v;
        if (i + 1 < NN) g_cursor[i + 1] = v;
    }
    if (i == 0) { g_rowptr[0] = 0; g_cursor[0] = 0; }
}

// ---------------- CSR build (counting sort by dst) ----------------
__global__ void k_scatter(const int* __restrict__ src, const int* __restrict__ dst) {
    int e = blockIdx.x * blockDim.x + threadIdx.x;
    if (e >= NE) return;
    int p = atomicAdd(&g_cursor[dst[e]], 1);
    g_adj[p] = ((ull)(unsigned)e << 32) | (unsigned)src[e];
}

// stabilize per-dst edge order by edge id (determinism of fp add order)
__global__ void k_sortadj() {
    __shared__ ull buf[8][128];
    int w = (blockIdx.x * blockDim.x + threadIdx.x) >> 5;
    int lane = threadIdx.x & 31;
    int lw = threadIdx.x >> 5;
    if (w >= NN) return;
    int s0 = g_rowptr[w];
    int cnt = g_rowptr[w + 1] - s0;
    if (cnt <= 1 || cnt > 128) return;
    ull* b = buf[lw];
    for (int i = lane; i < cnt; i += 32) b[i] = g_adj[s0 + i];
    __syncwarp();
    for (int p = 0; p < cnt; p++) {
        for (int l = (p & 1) + 2 * lane; l + 1 < cnt; l += 64) {
            ull a = b[l], c = b[l + 1];
            if (a > c) { b[l] = c; b[l + 1] = a; }
        }
        __syncwarp();
    }
    for (int i = lane; i < cnt; i += 32) g_adj[s0 + i] = b[i];
}

// ---------------- GEMM: [yl | yr] = A[N,K] @ [Wa | Wb] (Wa,Wb each K x 64) ----
// 64-row tile, 256 threads; thread (tx,ty) owns rows ty*4..+3, cols tx*4..+3 of
// both halves (R3-proven shape: 2 CTAs/SM, conflict-free LDS).
template<int K>
__global__ __launch_bounds__(256) void k_gemm(const float* __restrict__ A,
                                              const float* __restrict__ Wa,
                                              const float* __restrict__ Wb) {
    extern __shared__ float sm[];
    float* Ws = sm;             // K * 128  (cols 0..63 = Wa, 64..127 = Wb)
    float* As = sm + K * 128;   // K * APAD (272B rows, 16B-aligned, transposed)
    int tid = threadIdx.x;
    for (int idx = tid; idx < K * 64; idx += 256) {
        int k = idx >> 6, c = idx & 63;
        Ws[k * 128 + c] = Wa[idx];
        Ws[k * 128 + 64 + c] = Wb[idx];
    }
    int row0 = blockIdx.x * 64;
    for (int idx = tid; idx < 64 * K; idx += 256) {
        int r = idx / K, k = idx - r * K;
        int row = row0 + r;
        As[k * APAD + r] = (row < NN) ? A[row * K + k] : 0.f;
    }
    __syncthreads();
    int tx = tid & 15, ty = tid >> 4;
    ull accL[4][2], accR[4][2];
#pragma unroll
    for (int i = 0; i < 4; i++) {
        accL[i][0] = 0ull; accL[i][1] = 0ull;
        accR[i][0] = 0ull; accR[i][1] = 0ull;
    }

#pragma unroll 8
    for (int k = 0; k < K; k++) {
        float4 a = *(const float4*)&As[k * APAD + ty * 4];
        ulonglong2 wl = *(const ulonglong2*)&Ws[k * 128 + tx * 4];
        ulonglong2 wr = *(const ulonglong2*)&Ws[k * 128 + 64 + tx * 4];
        ull a0 = dup2(a.x), a1 = dup2(a.y), a2 = dup2(a.z), a3 = dup2(a.w);
        fma2(accL[0][0], a0, wl.x); fma2(accL[0][1], a0, wl.y);
        fma2(accR[0][0], a0, wr.x); fma2(accR[0][1], a0, wr.y);
        fma2(accL[1][0], a1, wl.x); fma2(accL[1][1], a1, wl.y);
        fma2(accR[1][0], a1, wr.x); fma2(accR[1][1], a1, wr.y);
        fma2(accL[2][0], a2, wl.x); fma2(accL[2][1], a2, wl.y);
        fma2(accR[2][0], a2, wr.x); fma2(accR[2][1], a2, wr.y);
        fma2(accL[3][0], a3, wl.x); fma2(accL[3][1], a3, wl.y);
        fma2(accR[3][0], a3, wr.x); fma2(accR[3][1], a3, wr.y);
    }
#pragma unroll
    for (int i = 0; i < 4; i++) {
        int row = row0 + ty * 4 + i;
        if (row < NN) {
            float2 l0 = unpk(accL[i][0]), l1 = unpk(accL[i][1]);
            float2 r0 = unpk(accR[i][0]), r1 = unpk(accR[i][1]);
            *(float4*)&g_yl[row * 64 + tx * 4] = make_float4(l0.x, l0.y, l1.x, l1.y);
            *(float4*)&g_yr[row * 64 + tx * 4] = make_float4(r0.x, r0.y, r1.x, r1.y);
        }
    }
}

// ---------------- segment aggregation (warp/node, half-warp/edge, 2x unroll) --
template<bool WEIGHTED>
__global__ void k_agg(const float* __restrict__ bias, float* __restrict__ hout) {
    int w = (blockIdx.x * blockDim.x + threadIdx.x) >> 5;
    int lane = threadIdx.x & 31;
    if (w >= NN) return;
    int grp = lane >> 4, sub = lane & 15;
    int s0 = g_rowptr[w], s1 = g_rowptr[w + 1];
    float4 acc0 = make_float4(0.f, 0.f, 0.f, 0.f);
    float4 acc1 = make_float4(0.f, 0.f, 0.f, 0.f);
    for (int p = s0 + grp; p < s1; p += 4) {
        ull ad0 = __ldg(&g_adj[p]);
        bool has1 = (p + 2 < s1);
        ull ad1 = has1 ? __ldg(&g_adj[p + 2]) : 0ull;
        int src0 = (int)(unsigned)ad0;
        int src1 = (int)(unsigned)ad1;
        float w0 = 0.f, w1 = 0.f;
        if (WEIGHTED) {
            w0 = __ldg(&g_ew[(int)(ad0 >> 32)]);
            w1 = has1 ? __ldg(&g_ew[(int)(ad1 >> 32)]) : 0.f;
        }
        if (!WEIGHTED || w0 != 0.f) {
            float4 v = *(const float4*)&g_yl[src0 * 64 + sub * 4];
            if (WEIGHTED) {
                acc0.x += w0 * v.x; acc0.y += w0 * v.y;
                acc0.z += w0 * v.z; acc0.w += w0 * v.w;
            } else {
                acc0.x += v.x; acc0.y += v.y; acc0.z += v.z; acc0.w += v.w;
            }
        }
        if (has1 && (!WEIGHTED || w1 != 0.f)) {
            float4 v = *(const float4*)&g_yl[src1 * 64 + sub * 4];
            if (WEIGHTED) {
                acc1.x += w1 * v.x; acc1.y += w1 * v.y;
                acc1.z += w1 * v.z; acc1.w += w1 * v.w;
            } else {
                acc1.x += v.x; acc1.y += v.y; acc1.z += v.z; acc1.w += v.w;
            }
        }
    }
    acc0.x += acc1.x; acc0.y += acc1.y; acc0.z += acc1.z; acc0.w += acc1.w;
    acc0.x += __shfl_xor_sync(0xffffffffu, acc0.x, 16);
    acc0.y += __shfl_xor_sync(0xffffffffu, acc0.y, 16);
    acc0.z += __shfl_xor_sync(0xffffffffu, acc0.z, 16);
    acc0.w += __shfl_xor_sync(0xffffffffu, acc0.w, 16);
    if (grp == 0) {
        float dg = fmaxf((float)(s1 - s0), 1.f);
        int c = sub * 4;
        float4 b  = *(const float4*)&bias[c];
        float4 yr = *(const float4*)&g_yr[w * 64 + c];
        float4 o;
        o.x = fmaxf(acc0.x / dg + b.x + yr.x, 0.f);
        o.y = fmaxf(acc0.y / dg + b.y + yr.y, 0.f);
        o.z = fmaxf(acc0.z / dg + b.z + yr.z, 0.f);
        o.w = fmaxf(acc0.w / dg + b.w + yr.w, 0.f);
        *(float4*)&hout[w * 64 + c] = o;
    }
}

// ---------------- edge scores via dst-CSR (h1[dst] register-stationary, 2x) ---
__global__ void k_score(const int* __restrict__ batch) {
    int w = (blockIdx.x * blockDim.x + threadIdx.x) >> 5;
    int lane = threadIdx.x & 31;
    if (w >= NN) return;
    int grp = lane >> 4, sub = lane & 15;
    unsigned hmask = 0xFFFFu << (grp * 16);
    int s0 = g_rowptr[w], s1 = g_rowptr[w + 1];
    float4 hd = *(const float4*)&g_h1[w * 64 + sub * 4];
    for (int p = s0 + grp; p < s1; p += 4) {
        ull ad0 = __ldg(&g_adj[p]);
        bool has1 = (p + 2 < s1);
        ull ad1 = has1 ? __ldg(&g_adj[p + 2]) : 0ull;
        int src0 = (int)(unsigned)ad0;
        int src1 = (int)(unsigned)ad1;
        float4 h0 = *(const float4*)&g_h1[src0 * 64 + sub * 4];
        float v0 = h0.x * hd.x + h0.y * hd.y + h0.z * hd.z + h0.w * hd.w;
        float v1 = 0.f;
        if (has1) {
            float4 h1v = *(const float4*)&g_h1[src1 * 64 + sub * 4];
            v1 = h1v.x * hd.x + h1v.y * hd.y + h1v.z * hd.z + h1v.w * hd.w;
        }
        v0 += __shfl_xor_sync(hmask, v0, 1);
        v1 += __shfl_xor_sync(hmask, v1, 1);
        v0 += __shfl_xor_sync(hmask, v0, 2);
        v1 += __shfl_xor_sync(hmask, v1, 2);
        v0 += __shfl_xor_sync(hmask, v0, 4);
        v1 += __shfl_xor_sync(hmask, v1, 4);
        v0 += __shfl_xor_sync(hmask, v0, 8);
        v1 += __shfl_xor_sync(hmask, v1, 8);
        if (sub == 0) {
            int eid0 = (int)(ad0 >> 32);
            g_scores[eid0] = v0;
            unsigned u = __float_as_uint(v0);
            u = (u & 0x80000000u) ? ~u : (u | 0x80000000u);
            ull key = ((ull)u << 32) | (unsigned)(~(unsigned)eid0);
            int g = __ldg(&batch[src0]);
            int pp = atomicAdd(&g_segcur[g], 1);
            g_buckets[pp] = key;
            if (has1) {
                int eid1 = (int)(ad1 >> 32);
                g_scores[eid1] = v1;
                unsigned u1 = __float_as_uint(v1);
                u1 = (u1 & 0x80000000u) ? ~u1 : (u1 | 0x80000000u);
                ull key1 = ((ull)u1 << 32) | (unsigned)(~(unsigned)eid1);
                int g1 = __ldg(&batch[src1]);
                int pp1 = atomicAdd(&g_segcur[g1], 1);
                g_buckets[pp1] = key1;
            }
        }
    }
}

// ---------------- per-graph exact top-k (bitonic sort of (score, eid) keys) ---
__global__ void k_topk(float* __restrict__ sampled) {
    extern __shared__ ull sk[];
    int g = blockIdx.x;
    int s0 = g_segptr[g];
    int n = g_segptr[g + 1] - s0;
    if (n <= 0) return;
    int m = 1;
    while (m < n) m <<= 1;
    if (m > 8192) m = 8192;           // safety; never hit for this data
    int nn2 = min(n, m);
    for (int i = threadIdx.x; i < m; i += blockDim.x)
        sk[i] = (i < nn2) ? g_buckets[s0 + i] : 0ull;
    __syncthreads();
    for (int k2 = 2; k2 <= m; k2 <<= 1) {
        for (int jj = k2 >> 1; jj > 0; jj >>= 1) {
            for (int i = threadIdx.x; i < m; i += blockDim.x) {
                int ij = i ^ jj;
                if (ij > i) {
                    ull a = sk[i], b = sk[ij];
                    bool desc = ((i & k2) == 0);
                    if (desc ? (a < b) : (a > b)) { sk[i] = b; sk[ij] = a; }
                }
            }
            __syncthreads();
        }
    }
    int k = (n + 1) >> 1;             // ceil(0.5 * n)
    for (int i = threadIdx.x; i < nn2; i += blockDim.x) {
        unsigned eid = ~(unsigned)(sk[i] & 0xffffffffu);
        float sel = (i < k) ? 1.f : 0.f;
        sampled[eid] = sel;
        g_ew[eid] = sel * g_scores[eid];
    }
}

// ---------------- pooling + MLP head (fused) ----------------
__global__ void k_poolhead(const float* __restrict__ W1, const float* __restrict__ b1,
                           const float* __restrict__ W2, const float* __restrict__ b2,
                           float* __restrict__ out) {
    __shared__ float p[64], z1[64], z2[10];
    int g = blockIdx.x, t = threadIdx.x;
    int s0 = g_nodeptr[g], s1 = g_nodeptr[g + 1];
    float acc = 0.f;
    for (int i = s0; i < s1; i++) acc += g_h1[i * 64 + t];   // h3 lives in g_h1
    p[t] = acc / fmaxf((float)(s1 - s0), 1.f);
    __syncthreads();
    float a1 = b1[t];
    for (int k = 0; k < 64; k++) a1 += p[k] * W1[k * 64 + t];
    z1[t] = fmaxf(a1, 0.f);
    __syncthreads();
    if (t < NC) {
        float a2 = b2[t];
        for (int k = 0; k < 64; k++) a2 += z1[k] * W2[k * 10 + t];
        z2[t] = a2;
    }
    __syncthreads();
    if (t == 0) {
        float mx = z2[0];
        for (int c = 1; c < NC; c++) mx = fmaxf(mx, z2[c]);
        float se = 0.f;
        for (int c = 0; c < NC; c++) se += expf(z2[c] - mx);
        float lse = mx + logf(se);
        for (int c = 0; c < NC; c++) out[g * NC + c] = z2[c] - lse;
    }
}

// ---------------- launcher ----------------
extern "C" void kernel_launch(void* const* d_in, const int* in_sizes, int n_in,
                              void* d_out, int out_size) {
    const float* x   = (const float*)d_in[0];
    const int*   ei  = (const int*)d_in[1];
    const int*   bat = (const int*)d_in[2];
    const float* W1l = (const float*)d_in[3];
    const float* b1l = (const float*)d_in[4];
    const float* W1r = (const float*)d_in[5];
    const float* W2l = (const float*)d_in[6];
    const float* b2l = (const float*)d_in[7];
    const float* W2r = (const float*)d_in[8];
    const float* W3l = (const float*)d_in[9];
    const float* b3l = (const float*)d_in[10];
    const float* W3r = (const float*)d_in[11];
    const float* Wl1 = (const float*)d_in[12];
    const float* bl1 = (const float*)d_in[13];
    const float* Wl2 = (const float*)d_in[14];
    const float* bl2 = (const float*)d_in[15];
    const int* src = ei;
    const int* dst = ei + NE;
    float* out_logits  = (float*)d_out;
    float* out_sampled = (float*)d_out + NG * NC;

    float *p_h1, *p_h2;
    cudaGetSymbolAddress((void**)&p_h1, g_h1);
    cudaGetSymbolAddress((void**)&p_h2, g_h2);

    cudaFuncSetAttribute((const void*)k_gemm<128>,
                         cudaFuncAttributeMaxDynamicSharedMemorySize, SMEM_G128);
    cudaFuncSetAttribute((const void*)k_gemm<64>,
                         cudaFuncAttributeMaxDynamicSharedMemorySize, SMEM_G64);
    cudaFuncSetAttribute((const void*)k_topk,
                         cudaFuncAttributeMaxDynamicSharedMemorySize, SMEM_TOPK);

    // side stream + events (created per call; capture-time only, replay uses graph)
    cudaStream_t s2;
    cudaStreamCreateWithFlags(&s2, cudaStreamNonBlocking);
    cudaEvent_t e0, e1, e2, e3;
    cudaEventCreateWithFlags(&e0, cudaEventDisableTiming);
    cudaEventCreateWithFlags(&e1, cudaEventDisableTiming);
    cudaEventCreateWithFlags(&e2, cudaEventDisableTiming);
    cudaEventCreateWithFlags(&e3, cudaEventDisableTiming);

    // ---- fork: structure build on s2, gemm128 on main ----
    cudaEventRecord(e0, 0);
    cudaStreamWaitEvent(s2, e0, 0);

    k_zero<<<196, 256, 0, s2>>>();                                  // 1
    k_hist<<<(NE + 255) / 256, 256, 0, s2>>>(src, dst, bat);        // 2
    k_scan_block<<<NB_SCAN, 1024, 0, s2>>>();                       // 3
    k_gemm<128><<<(NN + 63) / 64, 256, SMEM_G128>>>(x, W1l, W1r);   // 4 (main)
    k_scan_small<<<1, 1024, 0, s2>>>();                             // 5
    k_scan_addcur<<<196, 256, 0, s2>>>();                           // 6
    k_scatter<<<(NE + 255) / 256, 256, 0, s2>>>(src, dst);          // 7
    k_sortadj<<<(NN * 32 + 255) / 256, 256, 0, s2>>>();             // 8

    cudaEventRecord(e1, s2);
    cudaStreamWaitEvent(0, e1, 0);      // join

    // layer 1 aggregation (needs gemm128 + CSR)
    k_agg<false><<<(NN * 32 + 255) / 256, 256>>>(b1l, p_h1);        // 9

    // ---- fork: layer-2 gemm on s2, score+topk on main ----
    cudaEventRecord(e2, 0);
    cudaStreamWaitEvent(s2, e2, 0);

    k_gemm<64><<<(NN + 63) / 64, 256, SMEM_G64, s2>>>(p_h1, W2l, W2r); // 10
    k_score<<<(NN * 32 + 255) / 256, 256>>>(bat);                   // 11
    k_topk<<<NG, 512, SMEM_TOPK>>>(out_sampled);                    // 12

    cudaEventRecord(e3, s2);
    cudaStreamWaitEvent(0, e3, 0);      // join

    // layer 2 aggregation
    k_agg<true><<<(NN * 32 + 255) / 256, 256>>>(b2l, p_h2);         // 13

    // layer 3 (h3 -> g_h1)
    k_gemm<64><<<(NN + 63) / 64, 256, SMEM_G64>>>(p_h2, W3l, W3r);  // 14
    k_agg<true><<<(NN * 32 + 255) / 256, 256>>>(b3l, p_h1);         // 15

    // pooling + head
    k_poolhead<<<NG, 64>>>(Wl1, bl1, Wl2, bl2, out_logits);         // 16
}